// round 14
// baseline (speedup 1.0000x reference)
#include <cuda_runtime.h>

#define BDIM 8
#define NPTS 4096
#define DDIM 64
#define KNN 16
#define CELLS 512                        // 8(x) * 4(y) * 16(z), z-major
#define NZ 16
#define ZW 0.0625f                       // slab width 1/16
#define QPB 32                           // queries per block
#define STRIPS 4
#define P1T (QPB * STRIPS)               // 128 threads
#define TILE 512
#define SLICE (TILE / STRIPS)            // 128
#define DEPTH 16
#define GRP 8

typedef unsigned long long ull;

#define INF_KEY ((((ull)0x7F800000u) << 32) | 0xFFFFFFFFull)

__device__ int    g_knn[BDIM * NPTS * KNN];
__device__ float4 g_pts[BDIM * NPTS];          // cell-sorted (x,y,z,|p|^2)
__device__ int    g_oid[BDIM * NPTS];          // original index per sorted slot
__device__ int    g_cs[BDIM * (CELLS + 1)];    // cell start offsets

// key = (float_bits(d) << 32) | original_idx. d >= 0 -> unsigned compare ==
// exact lexicographic (d, idx) == jnp stable argsort; total order => scan
// order irrelevant.
__device__ __forceinline__ ull packK(float d, int m) {
    return ((ull)(unsigned)__float_as_uint(d) << 32) | (unsigned)m;
}

__device__ __forceinline__ void insertK(ull (&key)[KNN], ull ck) {
#pragma unroll
    for (int j = 0; j < KNN; j++) {
        bool lt = ck < key[j];
        ull o = key[j];
        key[j] = lt ? ck : o;
        ck     = lt ? o  : ck;
    }
}

__device__ __forceinline__ float pdist(float4 q, float4 c) {
    float t = q.x * c.x;
    t = fmaf(q.y, c.y, t);
    t = fmaf(q.z, c.z, t);
    return fmaf(-2.0f, t, q.w + c.w);   // identical fp order to passing rounds
}

// ---------------- Phase 0: grid build (16 z-slabs, z-major) -----------------
extern "C" __global__ void __launch_bounds__(512)
grid_build(const float* __restrict__ xyz)
{
    __shared__ int cnt[CELLS];
    __shared__ int cstart[CELLS + 1];
    __shared__ int ofs[CELLS];
    int b = blockIdx.x;
    int tid = threadIdx.x;
    const float* xb = xyz + (size_t)b * NPTS * 3;

    cnt[tid] = 0;
    __syncthreads();

    float px[8], py[8], pz[8]; int cell[8];
#pragma unroll
    for (int u = 0; u < 8; u++) {
        int n = tid + 512 * u;
        float x = xb[3*n], y = xb[3*n+1], z = xb[3*n+2];
        px[u] = x; py[u] = y; pz[u] = z;
        int cx = min(7, (int)(x * 8.0f));
        int cy = min(3, (int)(y * 4.0f));
        int cz = min(NZ - 1, (int)(z * 16.0f));
        cell[u] = cx + 8 * cy + 32 * cz;        // z-major: slabs contiguous
        atomicAdd(&cnt[cell[u]], 1);
    }
    __syncthreads();

    for (int off = 1; off < CELLS; off <<= 1) {
        int v = (tid >= off) ? cnt[tid - off] : 0;
        __syncthreads();
        cnt[tid] += v;
        __syncthreads();
    }
    if (tid == 0) cstart[0] = 0;
    cstart[tid + 1] = cnt[tid];
    __syncthreads();
    ofs[tid] = cstart[tid];
    g_cs[b * (CELLS + 1) + tid] = cstart[tid];
    if (tid == 511) g_cs[b * (CELLS + 1) + 512] = cstart[512];
    __syncthreads();

#pragma unroll
    for (int u = 0; u < 8; u++) {
        int slot = atomicAdd(&ofs[cell[u]], 1);
        float s = px[u] * px[u];
        s = fmaf(py[u], py[u], s);
        s = fmaf(pz[u], pz[u], s);           // same chain as query side
        g_pts[(size_t)b * NPTS + slot] = make_float4(px[u], py[u], pz[u], s);
        g_oid[(size_t)b * NPTS + slot] = tid + 512 * u;
    }
}

// ---------------- Phase 1: slab-restricted exact top-16 ---------------------
// Slabs z +/- 2 (width 1/16) = ONE CONTIGUOUS sorted range (~1536 candidates,
// 40% less than R13). Center-out 512-pt tiles; validated scan machinery;
// tree strip-merge (s1->s0 || s3->s2, then s2->s0). Guard + exact fallback.
#define QK_SMEM (TILE*16 + TILE*4 + DEPTH*P1T*8)   // 8K + 2K + 16K = 26K

extern "C" __global__ void __launch_bounds__(P1T)
knn_query()
{
    extern __shared__ char smem_raw[];
    float4* cand = (float4*)smem_raw;                        // [TILE]
    int*    soid = (int*)(smem_raw + TILE * 16);             // [TILE]
    ull*    buf  = (ull*)(smem_raw + TILE * 16 + TILE * 4);  // [DEPTH][P1T]

    int blkq = blockIdx.x & 127;
    int b    = blockIdx.x >> 7;
    int tid  = threadIdx.x;
    int lq   = tid & (QPB - 1);
    int s    = tid >> 5;                 // strip 0..3 (warp-uniform)

    const int* cs = g_cs + b * (CELLS + 1);
    size_t pb = (size_t)b * NPTS;

    int qslot = blkq * QPB + lq;
    float4 q = g_pts[pb + qslot];
    int oid  = g_oid[pb + qslot];

    // Block z-range (each warp holds all 32 queries -> identical reduction).
    int slab = min(NZ - 1, (int)(q.z * 16.0f));
    int zmn = slab, zmx = slab;
#pragma unroll
    for (int o = 16; o > 0; o >>= 1) {
        int a1 = __shfl_xor_sync(0xffffffffu, zmn, o);
        int a2 = __shfl_xor_sync(0xffffffffu, zmx, o);
        zmn = min(zmn, a1); zmx = max(zmx, a2);
    }
    int z0 = max(0, zmn - 2), z1 = min(NZ - 1, zmx + 2);
    int lo = cs[32 * z0], hi = cs[32 * z1 + 32];   // contiguous slab range
    int C  = hi - lo;
    int ntiles = (C + TILE - 1) >> 9;
    int tqm = (blkq * QPB + 16 - lo) >> 9;          // tile holding the queries
    tqm = min(max(tqm, 0), ntiles - 1);

    ull key[KNN];
#pragma unroll
    for (int j = 0; j < KNN; j++) key[j] = INF_KEY;

    unsigned bufA = (unsigned)__cvta_generic_to_shared(buf) + tid * 8u;
    int cnt = 0;
    float thr = 3.0e38f;
    int up = tqm + 1, dn = tqm - 1;

#pragma unroll 1
    for (int j = 0; j < ntiles; j++) {
        int t;                            // center-out tile order
        if (j == 0) t = tqm;
        else if (up < ntiles && ((j & 1) == 1 || dn < 0)) t = up++;
        else t = dn--;

        __syncthreads();                  // previous tile fully consumed
#pragma unroll
        for (int r = 0; r < TILE / P1T; r++) {     // trivial coalesced copy
            int i = r * P1T + tid;
            int e = t * TILE + i;
            if (e < C) {
                cand[i] = g_pts[pb + lo + e];
                soid[i] = g_oid[pb + lo + e];
            } else {
                cand[i] = make_float4(0.0f, 0.0f, 0.0f, 3.0e38f);
                soid[i] = 0x7fffffff;
            }
        }
        __syncthreads();

        int c0 = s * SLICE;
        int start = 0;
        if (j == 0) {                     // seed: 16 convergent inserts
#pragma unroll 1
            for (int i = c0; i < c0 + KNN; i++)
                insertK(key, packK(pdist(q, cand[i]), soid[i]));
            start = KNN;
            thr = __uint_as_float((unsigned)(key[KNN - 1] >> 32));
        }

#pragma unroll 1
        for (int i0 = c0 + start; i0 < c0 + SLICE; i0 += GRP) {
            if (__any_sync(0xffffffffu, cnt > DEPTH - GRP)) {   // drain
                asm volatile("" ::: "memory");
                int cm = cnt;
#pragma unroll
                for (int o = 16; o > 0; o >>= 1) {
                    int t2 = __shfl_xor_sync(0xffffffffu, cm, o);
                    cm = cm > t2 ? cm : t2;
                }
#pragma unroll 2
                for (int jj = 0; jj < cm; jj++) {
                    ull ck = (jj < cnt) ? buf[jj * P1T + tid] : INF_KEY;
                    insertK(key, ck);
                }
                cnt = 0;
                thr = __uint_as_float((unsigned)(key[KNN - 1] >> 32));
            }

            float dv[GRP]; int iv[GRP];
#pragma unroll
            for (int u = 0; u < GRP; u++) {      // 8 independent chains
                dv[u] = pdist(q, cand[i0 + u]);
                iv[u] = soid[i0 + u];
            }
            unsigned h[GRP];
#pragma unroll
            for (int u = 0; u < GRP; u++) h[u] = (dv[u] <= thr);

            unsigned o1 = h[0];
            unsigned s01 = h[0]+h[1], s23 = h[2]+h[3], s45 = h[4]+h[5];
            unsigned o2 = s01, o3 = s01 + h[2], o4 = s01 + s23;
            unsigned o5 = o4 + h[4], o6 = o4 + s45, o7 = o6 + h[6];
            unsigned tot = o7 + h[7];
            unsigned off[GRP] = {0, o1, o2, o3, o4, o5, o6, o7};

#pragma unroll
            for (int u = 0; u < GRP; u++) {      // predicated STS, no clobber
                unsigned ad = bufA + ((unsigned)(cnt + off[u]) << 10); // *P1T*8
                asm volatile(
                    "{\n\t.reg .pred p;\n\t"
                    "setp.ne.u32 p, %0, 0;\n\t"
                    "@p st.shared.v2.u32 [%1], {%2, %3};\n\t}"
                    :: "r"(h[u]), "r"(ad),
                       "r"((unsigned)iv[u]), "r"(__float_as_uint(dv[u])));
            }
            cnt += tot;
        }
    }

    // Final drain.
    asm volatile("" ::: "memory");
    {
        int cm = cnt;
#pragma unroll
        for (int o = 16; o > 0; o >>= 1) {
            int t2 = __shfl_xor_sync(0xffffffffu, cm, o);
            cm = cm > t2 ? cm : t2;
        }
#pragma unroll 2
        for (int jj = 0; jj < cm; jj++) {
            ull ck = (jj < cnt) ? buf[jj * P1T + tid] : INF_KEY;
            insertK(key, ck);
        }
    }

    // Tree strip-merge through smem (buf drained -> reuse as pairs).
    // Round 1: s1 -> s0 and s3 -> s2 in parallel. Round 2: s2 -> s0.
    ull* pairs = buf;
    __syncthreads();
    if (s & 1) {                         // s = 1, 3 publish
#pragma unroll
        for (int jj = 0; jj < KNN; jj++)
            pairs[((s >> 1) * QPB + lq) * KNN + jj] = key[jj];
    }
    __syncthreads();
    if (!(s & 1)) {                      // s = 0, 2 merge partner
#pragma unroll
        for (int jj = 0; jj < KNN; jj++)
            insertK(key, pairs[((s >> 1) * QPB + lq) * KNN + jj]);
    }
    __syncthreads();
    if (s == 2) {                        // s2 publishes merged {2,3}
#pragma unroll
        for (int jj = 0; jj < KNN; jj++)
            pairs[(2 * QPB + lq) * KNN + jj] = key[jj];
    }
    __syncthreads();

    if (s == 0) {
#pragma unroll
        for (int jj = 0; jj < KNN; jj++)
            insertK(key, pairs[(2 * QPB + lq) * KNN + jj]);

        // Guard: all points outside the z-region are farther than g.
        float d16 = __uint_as_float((unsigned)(key[KNN - 1] >> 32));
        float g = 1.0e30f;
        if (z0 > 0)      g = fminf(g, q.z - (float)z0 * ZW);
        if (z1 < NZ - 1) g = fminf(g, (float)(z1 + 1) * ZW - q.z);
        g -= 1.0e-3f;
        if (!(d16 <= g * g)) {           // exact fallback (rare, ~1e-3/query)
#pragma unroll
            for (int jj = 0; jj < KNN; jj++) key[jj] = INF_KEY;
#pragma unroll 1
            for (int m = 0; m < NPTS; m++) {
                ull ck = packK(pdist(q, g_pts[pb + m]), g_oid[pb + m]);
                if (ck < key[KNN - 1]) insertK(key, ck);
            }
        }

        int4* kp = (int4*)(g_knn + (pb + oid) * KNN);
        kp[0] = make_int4((int)(unsigned)key[0],  (int)(unsigned)key[1],
                          (int)(unsigned)key[2],  (int)(unsigned)key[3]);
        kp[1] = make_int4((int)(unsigned)key[4],  (int)(unsigned)key[5],
                          (int)(unsigned)key[6],  (int)(unsigned)key[7]);
        kp[2] = make_int4((int)(unsigned)key[8],  (int)(unsigned)key[9],
                          (int)(unsigned)key[10], (int)(unsigned)key[11]);
        kp[3] = make_int4((int)(unsigned)key[12], (int)(unsigned)key[13],
                          (int)(unsigned)key[14], (int)(unsigned)key[15]);
    }
}

// ---------------- Phase 2: MLP + staged transpose-add epilogue --------------
// BYTE-IDENTICAL to R11/R13 (measured 104.5 us, regs=128, 4 blocks/SM).
#define MLP_SMEM_FLOATS (DDIM*DDIM + 4*DDIM + DDIM + 128*DDIM)

extern "C" __global__ void __launch_bounds__(128, 4)
mlp_kernel(const float* __restrict__ xyz, const float* __restrict__ x,
           const float* __restrict__ W1, const float* __restrict__ b1,
           const float* __restrict__ W2, const float* __restrict__ b2,
           float* __restrict__ out)
{
    extern __shared__ float sm[];
    float*  W2s = sm;
    float4* W1p = (float4*)(sm + DDIM*DDIM);
    float*  b2s = sm + DDIM*DDIM + 4*DDIM;
    float*  stg = sm + DDIM*DDIM + 4*DDIM + DDIM;

    int tid = threadIdx.x;
    for (int i = tid; i < DDIM*DDIM; i += 128) W2s[i] = W2[i];
    if (tid < DDIM) {
        W1p[tid] = make_float4(W1[tid], W1[DDIM + tid], W1[2*DDIM + tid], b1[tid]);
        b2s[tid] = b2[tid];
    }
    __syncthreads();

    int kh = blockIdx.x & 1;
    int nt = (blockIdx.x >> 1) & 255;
    int b  = blockIdx.x >> 9;
    int j  = tid & 15;
    int qp = (tid >> 4) & 1;
    int eh = tid >> 5;
    int n  = nt * 16 + j;

    const int* kr = g_knn + (((size_t)b * NPTS + n) << 4) + kh * 8 + qp;
    const float* xb = xyz + (size_t)b * NPTS * 3;
    float px = xb[3*n], py = xb[3*n+1], pz = xb[3*n+2];

    float dx[4], dy[4], dz[4];
#pragma unroll
    for (int u = 0; u < 4; u++) {
        int m = kr[2 * u];
        dx[u] = px - xb[3*m];
        dy[u] = py - xb[3*m+1];
        dz[u] = pz - xb[3*m+2];
    }

    ull acc[4][8];
    const ull* b2p = (const ull*)(b2s + (eh << 4));
#pragma unroll
    for (int u = 0; u < 4; u++)
#pragma unroll
        for (int e = 0; e < 8; e++) acc[u][e] = b2p[e];

#pragma unroll 4
    for (int d = 0; d < DDIM; d++) {
        float4 w1 = W1p[d];
        float h[4];
        unsigned z = 1;
#pragma unroll
        for (int u = 0; u < 4; u++) {
            h[u] = fmaf(dz[u], w1.z, fmaf(dy[u], w1.y, fmaf(dx[u], w1.x, w1.w)));
            h[u] = fmaxf(h[u], 0.0f);
            z &= (h[u] == 0.0f);
        }
        if (__all_sync(0xffffffffu, z)) continue;
        ull h2[4];
#pragma unroll
        for (int u = 0; u < 4; u++)
            asm("mov.b64 %0, {%1, %1};" : "=l"(h2[u]) : "r"(__float_as_int(h[u])));
        const ulonglong2* w = (const ulonglong2*)(W2s + (d << 6) + (eh << 4));
#pragma unroll
        for (int e = 0; e < 4; e++) {
            ulonglong2 wv = w[e];
#pragma unroll
            for (int u = 0; u < 4; u++) {
                asm("fma.rn.f32x2 %0, %1, %2, %0;" : "+l"(acc[u][2*e])   : "l"(h2[u]), "l"(wv.x));
                asm("fma.rn.f32x2 %0, %1, %2, %0;" : "+l"(acc[u][2*e+1]) : "l"(h2[u]), "l"(wv.y));
            }
        }
    }

    ulonglong2* st2 = (ulonglong2*)stg;
#pragma unroll
    for (int u = 0; u < 4; u++) {
        int r = (qp + 2 * u) * 16 + j;
#pragma unroll
        for (int e = 0; e < 4; e++) {
            int c4 = (eh << 2) + e;
            ulonglong2 v; v.x = acc[u][2*e]; v.y = acc[u][2*e+1];
            st2[r * 16 + (c4 ^ (r & 15))] = v;
        }
    }
    __syncthreads();

    const ulonglong2* xg = (const ulonglong2*)x;
    ulonglong2*       og = (ulonglong2*)out;
#pragma unroll
    for (int i = 0; i < 16; i++) {
        int f    = tid + 128 * i;
        int c4   = f & 15;
        int row  = f >> 4;
        int kk   = kh * 8 + (row >> 4);
        int jj   = row & 15;
        ulonglong2 pv = st2[row * 16 + (c4 ^ (row & 15))];
        size_t gi = ((((size_t)b * KNN + kk) * NPTS) + nt * 16 + jj) * 16 + c4;
        ulonglong2 xv = xg[gi];
        ulonglong2 r;
        asm("add.rn.f32x2 %0, %1, %2;" : "=l"(r.x) : "l"(pv.x), "l"(xv.x));
        asm("add.rn.f32x2 %0, %1, %2;" : "=l"(r.y) : "l"(pv.y), "l"(xv.y));
        og[gi] = r;
    }
}

extern "C" void kernel_launch(void* const* d_in, const int* in_sizes, int n_in,
                              void* d_out, int out_size) {
    const float* xyz = (const float*)d_in[0];
    const float* x   = (const float*)d_in[1];
    const float* W1  = (const float*)d_in[2];
    const float* b1  = (const float*)d_in[3];
    const float* W2  = (const float*)d_in[4];
    const float* b2  = (const float*)d_in[5];
    float* out = (float*)d_out;

    cudaFuncSetAttribute(knn_query, cudaFuncAttributeMaxDynamicSharedMemorySize,
                         QK_SMEM);
    cudaFuncSetAttribute(mlp_kernel, cudaFuncAttributeMaxDynamicSharedMemorySize,
                         MLP_SMEM_FLOATS * (int)sizeof(float));

    grid_build<<<BDIM, 512>>>(xyz);
    knn_query<<<BDIM * (NPTS / QPB), P1T, QK_SMEM>>>();
    mlp_kernel<<<BDIM * 256 * 2, 128, MLP_SMEM_FLOATS * sizeof(float)>>>(
        xyz, x, W1, b1, W2, b2, out);
}

// round 15
// speedup vs baseline: 2.5248x; 2.5248x over previous
#include <cuda_runtime.h>

#define BDIM 8
#define NPTS 4096
#define DDIM 64
#define KNN 16
#define GDIM 8
#define CELLS 512                        // 8x8x8, z-major rows of 64
#define QPB 32                           // queries per block
#define STRIPS 4
#define P1T (QPB * STRIPS)               // 128 threads
#define TILE 512
#define SLICE (TILE / STRIPS)            // 128
#define DEPTH 16
#define GRP 8

typedef unsigned long long ull;

#define INF_KEY ((((ull)0x7F800000u) << 32) | 0xFFFFFFFFull)

__device__ int    g_knn[BDIM * NPTS * KNN];
__device__ float4 g_pts[BDIM * NPTS];          // cell-sorted (x,y,z,|p|^2)
__device__ int    g_oid[BDIM * NPTS];          // original index per sorted slot
__device__ int    g_cs[BDIM * (CELLS + 1)];    // cell start offsets

// key = (float_bits(d) << 32) | original_idx. d >= 0 -> unsigned compare ==
// exact lexicographic (d, idx) == jnp stable argsort; total order => scan
// order irrelevant.
__device__ __forceinline__ ull packK(float d, int m) {
    return ((ull)(unsigned)__float_as_uint(d) << 32) | (unsigned)m;
}

__device__ __forceinline__ void insertK(ull (&key)[KNN], ull ck) {
#pragma unroll
    for (int j = 0; j < KNN; j++) {
        bool lt = ck < key[j];
        ull o = key[j];
        key[j] = lt ? ck : o;
        ck     = lt ? o  : ck;
    }
}

__device__ __forceinline__ float pdist(float4 q, float4 c) {
    float t = q.x * c.x;
    t = fmaf(q.y, c.y, t);
    t = fmaf(q.z, c.z, t);
    return fmaf(-2.0f, t, q.w + c.w);   // identical fp order to passing rounds
}

// ---------------- Phase 0: grid build (R13 geometry: 8 z-slabs) -------------
extern "C" __global__ void __launch_bounds__(512)
grid_build(const float* __restrict__ xyz)
{
    __shared__ int cnt[CELLS];
    __shared__ int cstart[CELLS + 1];
    __shared__ int ofs[CELLS];
    int b = blockIdx.x;
    int tid = threadIdx.x;
    const float* xb = xyz + (size_t)b * NPTS * 3;

    cnt[tid] = 0;
    __syncthreads();

    float px[8], py[8], pz[8]; int cell[8];
#pragma unroll
    for (int u = 0; u < 8; u++) {
        int n = tid + 512 * u;
        float x = xb[3*n], y = xb[3*n+1], z = xb[3*n+2];
        px[u] = x; py[u] = y; pz[u] = z;
        int cx = min(GDIM - 1, (int)(x * 8.0f));
        int cy = min(GDIM - 1, (int)(y * 8.0f));
        int cz = min(GDIM - 1, (int)(z * 8.0f));
        cell[u] = cx + 8 * cy + 64 * cz;        // z-major: slabs contiguous
        atomicAdd(&cnt[cell[u]], 1);
    }
    __syncthreads();

    for (int off = 1; off < CELLS; off <<= 1) {
        int v = (tid >= off) ? cnt[tid - off] : 0;
        __syncthreads();
        cnt[tid] += v;
        __syncthreads();
    }
    if (tid == 0) cstart[0] = 0;
    cstart[tid + 1] = cnt[tid];
    __syncthreads();
    ofs[tid] = cstart[tid];
    g_cs[b * (CELLS + 1) + tid] = cstart[tid];
    if (tid == 511) g_cs[b * (CELLS + 1) + 512] = cstart[512];
    __syncthreads();

#pragma unroll
    for (int u = 0; u < 8; u++) {
        int slot = atomicAdd(&ofs[cell[u]], 1);
        float s = px[u] * px[u];
        s = fmaf(py[u], py[u], s);
        s = fmaf(pz[u], pz[u], s);           // same chain as query side
        g_pts[(size_t)b * NPTS + slot] = make_float4(px[u], py[u], pz[u], s);
        g_oid[(size_t)b * NPTS + slot] = tid + 512 * u;
    }
}

// ---------------- Phase 1: slab-restricted exact top-16 (R13 + tree merge) --
#define QK_SMEM (TILE*16 + TILE*4 + DEPTH*P1T*8)   // 8K + 2K + 16K = 26K

extern "C" __global__ void __launch_bounds__(P1T)
knn_query()
{
    extern __shared__ char smem_raw[];
    float4* cand = (float4*)smem_raw;                        // [TILE]
    int*    soid = (int*)(smem_raw + TILE * 16);             // [TILE]
    ull*    buf  = (ull*)(smem_raw + TILE * 16 + TILE * 4);  // [DEPTH][P1T]

    int blkq = blockIdx.x & 127;
    int b    = blockIdx.x >> 7;
    int tid  = threadIdx.x;
    int lq   = tid & (QPB - 1);
    int s    = tid >> 5;                 // strip 0..3 (warp-uniform)

    const int* cs = g_cs + b * (CELLS + 1);
    size_t pb = (size_t)b * NPTS;

    int qslot = blkq * QPB + lq;
    float4 q = g_pts[pb + qslot];
    int oid  = g_oid[pb + qslot];

    // Block z-range (each warp holds all 32 queries -> identical reduction).
    int slab = min(7, (int)(q.z * 8.0f));
    int zmn = slab, zmx = slab;
#pragma unroll
    for (int o = 16; o > 0; o >>= 1) {
        int a1 = __shfl_xor_sync(0xffffffffu, zmn, o);
        int a2 = __shfl_xor_sync(0xffffffffu, zmx, o);
        zmn = min(zmn, a1); zmx = max(zmx, a2);
    }
    int z0 = max(0, zmn - 2), z1 = min(7, zmx + 2);
    int lo = cs[64 * z0], hi = cs[64 * z1 + 64];   // contiguous slab range
    int C  = hi - lo;
    int ntiles = (C + TILE - 1) >> 9;
    int tqm = (blkq * QPB + 16 - lo) >> 9;          // tile holding the queries
    tqm = min(max(tqm, 0), ntiles - 1);

    ull key[KNN];
#pragma unroll
    for (int j = 0; j < KNN; j++) key[j] = INF_KEY;

    unsigned bufA = (unsigned)__cvta_generic_to_shared(buf) + tid * 8u;
    int cnt = 0;
    float thr = 3.0e38f;
    int up = tqm + 1, dn = tqm - 1;

#pragma unroll 1
    for (int j = 0; j < ntiles; j++) {
        int t;                            // center-out tile order
        if (j == 0) t = tqm;
        else if (up < ntiles && ((j & 1) == 1 || dn < 0)) t = up++;
        else t = dn--;

        __syncthreads();                  // previous tile fully consumed
#pragma unroll
        for (int r = 0; r < TILE / P1T; r++) {     // trivial coalesced copy
            int i = r * P1T + tid;
            int e = t * TILE + i;
            if (e < C) {
                cand[i] = g_pts[pb + lo + e];
                soid[i] = g_oid[pb + lo + e];
            } else {
                cand[i] = make_float4(0.0f, 0.0f, 0.0f, 3.0e38f);
                soid[i] = 0x7fffffff;
            }
        }
        __syncthreads();

        int c0 = s * SLICE;
        int start = 0;
        if (j == 0) {                     // seed: 16 convergent inserts
#pragma unroll 1
            for (int i = c0; i < c0 + KNN; i++)
                insertK(key, packK(pdist(q, cand[i]), soid[i]));
            start = KNN;
            thr = __uint_as_float((unsigned)(key[KNN - 1] >> 32));
        }

#pragma unroll 1
        for (int i0 = c0 + start; i0 < c0 + SLICE; i0 += GRP) {
            if (__any_sync(0xffffffffu, cnt > DEPTH - GRP)) {   // drain
                asm volatile("" ::: "memory");
                int cm = cnt;
#pragma unroll
                for (int o = 16; o > 0; o >>= 1) {
                    int t2 = __shfl_xor_sync(0xffffffffu, cm, o);
                    cm = cm > t2 ? cm : t2;
                }
#pragma unroll 2
                for (int jj = 0; jj < cm; jj++) {
                    ull ck = (jj < cnt) ? buf[jj * P1T + tid] : INF_KEY;
                    insertK(key, ck);
                }
                cnt = 0;
                thr = __uint_as_float((unsigned)(key[KNN - 1] >> 32));
            }

            float dv[GRP]; int iv[GRP];
#pragma unroll
            for (int u = 0; u < GRP; u++) {      // 8 independent chains
                dv[u] = pdist(q, cand[i0 + u]);
                iv[u] = soid[i0 + u];
            }
            unsigned h[GRP];
#pragma unroll
            for (int u = 0; u < GRP; u++) h[u] = (dv[u] <= thr);

            unsigned o1 = h[0];
            unsigned s01 = h[0]+h[1], s23 = h[2]+h[3], s45 = h[4]+h[5];
            unsigned o2 = s01, o3 = s01 + h[2], o4 = s01 + s23;
            unsigned o5 = o4 + h[4], o6 = o4 + s45, o7 = o6 + h[6];
            unsigned tot = o7 + h[7];
            unsigned off[GRP] = {0, o1, o2, o3, o4, o5, o6, o7};

#pragma unroll
            for (int u = 0; u < GRP; u++) {      // predicated STS, no clobber
                unsigned ad = bufA + ((unsigned)(cnt + off[u]) << 10); // *P1T*8
                asm volatile(
                    "{\n\t.reg .pred p;\n\t"
                    "setp.ne.u32 p, %0, 0;\n\t"
                    "@p st.shared.v2.u32 [%1], {%2, %3};\n\t}"
                    :: "r"(h[u]), "r"(ad),
                       "r"((unsigned)iv[u]), "r"(__float_as_uint(dv[u])));
            }
            cnt += tot;
        }
    }

    // Final drain.
    asm volatile("" ::: "memory");
    {
        int cm = cnt;
#pragma unroll
        for (int o = 16; o > 0; o >>= 1) {
            int t2 = __shfl_xor_sync(0xffffffffu, cm, o);
            cm = cm > t2 ? cm : t2;
        }
#pragma unroll 2
        for (int jj = 0; jj < cm; jj++) {
            ull ck = (jj < cnt) ? buf[jj * P1T + tid] : INF_KEY;
            insertK(key, ck);
        }
    }

    // Tree strip-merge: s1->s0 || s3->s2, then s2->s0 (exact set merge).
    ull* pairs = buf;
    __syncthreads();
    if (s & 1) {
#pragma unroll
        for (int jj = 0; jj < KNN; jj++)
            pairs[((s >> 1) * QPB + lq) * KNN + jj] = key[jj];
    }
    __syncthreads();
    if (!(s & 1)) {
#pragma unroll
        for (int jj = 0; jj < KNN; jj++)
            insertK(key, pairs[((s >> 1) * QPB + lq) * KNN + jj]);
    }
    __syncthreads();
    if (s == 2) {
#pragma unroll
        for (int jj = 0; jj < KNN; jj++)
            pairs[(2 * QPB + lq) * KNN + jj] = key[jj];
    }
    __syncthreads();

    if (s == 0) {
#pragma unroll
        for (int jj = 0; jj < KNN; jj++)
            insertK(key, pairs[(2 * QPB + lq) * KNN + jj]);

        // Guard: all points outside the z-region are farther than g.
        float d16 = __uint_as_float((unsigned)(key[KNN - 1] >> 32));
        float g = 1.0e30f;
        if (z0 > 0) g = fminf(g, q.z - (float)z0 * 0.125f);
        if (z1 < 7) g = fminf(g, (float)(z1 + 1) * 0.125f - q.z);
        g -= 1.0e-3f;
        if (!(d16 <= g * g)) {           // exact fallback (~never at 0.25 margin)
#pragma unroll
            for (int jj = 0; jj < KNN; jj++) key[jj] = INF_KEY;
#pragma unroll 1
            for (int m = 0; m < NPTS; m++) {
                ull ck = packK(pdist(q, g_pts[pb + m]), g_oid[pb + m]);
                if (ck < key[KNN - 1]) insertK(key, ck);
            }
        }

        int4* kp = (int4*)(g_knn + (pb + oid) * KNN);
        kp[0] = make_int4((int)(unsigned)key[0],  (int)(unsigned)key[1],
                          (int)(unsigned)key[2],  (int)(unsigned)key[3]);
        kp[1] = make_int4((int)(unsigned)key[4],  (int)(unsigned)key[5],
                          (int)(unsigned)key[6],  (int)(unsigned)key[7]);
        kp[2] = make_int4((int)(unsigned)key[8],  (int)(unsigned)key[9],
                          (int)(unsigned)key[10], (int)(unsigned)key[11]);
        kp[3] = make_int4((int)(unsigned)key[12], (int)(unsigned)key[13],
                          (int)(unsigned)key[14], (int)(unsigned)key[15]);
    }
}

// ---------------- Phase 2: MLP, two-pass h-sharing --------------------------
// Pass A (thread = point): H[64][128] into the reused staging area + 64-bit
// nonzero-row bitmap. Main loop reads h via broadcast LDS (no recompute, 4x
// dedup); dead rows cost ~2 instr. Same fp chains, same accumulate order,
// skips only exact zeros -> bit-identical output.
#define MLP_SMEM_FLOATS (DDIM*DDIM + 4*DDIM + DDIM + 128*DDIM)   // 50KB

extern "C" __global__ void __launch_bounds__(128, 4)
mlp_kernel(const float* __restrict__ xyz, const float* __restrict__ x,
           const float* __restrict__ W1, const float* __restrict__ b1,
           const float* __restrict__ W2, const float* __restrict__ b2,
           float* __restrict__ out)
{
    extern __shared__ float sm[];
    float*  W2s = sm;                                // 4096
    float4* W1p = (float4*)(sm + DDIM*DDIM);         // 64 float4
    float*  b2s = sm + DDIM*DDIM + 4*DDIM;           // 64
    float*  stg = sm + DDIM*DDIM + 4*DDIM + DDIM;    // 128x64: H, then staging
    __shared__ ull zw[4];

    int tid = threadIdx.x;
    for (int i = tid; i < DDIM*DDIM; i += 128) W2s[i] = W2[i];
    if (tid < DDIM) {
        W1p[tid] = make_float4(W1[tid], W1[DDIM + tid], W1[2*DDIM + tid], b1[tid]);
        b2s[tid] = b2[tid];
    }
    __syncthreads();

    int kh = blockIdx.x & 1;
    int nt = (blockIdx.x >> 1) & 255;
    int b  = blockIdx.x >> 9;
    const float* xb = xyz + (size_t)b * NPTS * 3;

    // ---- Pass A: thread = point p (klocal = p>>4, j = p&15) ----
    {
        int p  = tid;
        int jA = p & 15;
        int nA = nt * 16 + jA;
        int kA = kh * 8 + (p >> 4);
        int m  = g_knn[(((size_t)b * NPTS + nA) << 4) + kA];
        float dxA = xb[3*nA]   - xb[3*m];
        float dyA = xb[3*nA+1] - xb[3*m+1];
        float dzA = xb[3*nA+2] - xb[3*m+2];

        ull nzm = 0;
#pragma unroll 4
        for (int d = 0; d < DDIM; d++) {
            float4 w1 = W1p[d];
            float h = fmaf(dzA, w1.z, fmaf(dyA, w1.y, fmaf(dxA, w1.x, w1.w)));
            h = fmaxf(h, 0.0f);               // identical chain to R13
            stg[d * 128 + p] = h;
            nzm |= (h != 0.0f) ? (1ull << d) : 0ull;
        }
#pragma unroll
        for (int o = 16; o > 0; o >>= 1)
            nzm |= __shfl_xor_sync(0xffffffffu, nzm, o);
        if ((tid & 31) == 0) zw[tid >> 5] = nzm;
    }
    __syncthreads();
    ull nzall = zw[0] | zw[1] | zw[2] | zw[3];

    // ---- Main: thread = (j, qp, eh), 4 points x quarter columns ----
    int j  = tid & 15;
    int qp = (tid >> 4) & 1;
    int eh = tid >> 5;                 // warp-uniform

    ull acc[4][8];
    const ull* b2p = (const ull*)(b2s + (eh << 4));
#pragma unroll
    for (int u = 0; u < 4; u++)
#pragma unroll
        for (int e = 0; e < 8; e++) acc[u][e] = b2p[e];

#pragma unroll 4
    for (int d = 0; d < DDIM; d++) {
        if (!((nzall >> d) & 1ull)) continue;   // block-uniform dead-row skip
        ull h2[4];
#pragma unroll
        for (int u = 0; u < 4; u++) {
            float hv = stg[d * 128 + (qp + 2 * u) * 16 + j];  // broadcast LDS
            asm("mov.b64 %0, {%1, %1};" : "=l"(h2[u]) : "r"(__float_as_int(hv)));
        }
        const ulonglong2* w = (const ulonglong2*)(W2s + (d << 6) + (eh << 4));
#pragma unroll
        for (int e = 0; e < 4; e++) {
            ulonglong2 wv = w[e];   // broadcast LDS.128
#pragma unroll
            for (int u = 0; u < 4; u++) {
                asm("fma.rn.f32x2 %0, %1, %2, %0;" : "+l"(acc[u][2*e])   : "l"(h2[u]), "l"(wv.x));
                asm("fma.rn.f32x2 %0, %1, %2, %0;" : "+l"(acc[u][2*e+1]) : "l"(h2[u]), "l"(wv.y));
            }
        }
    }
    __syncthreads();                       // H fully consumed before overwrite

    // Stage quarter-rows (XOR-swizzled float4 columns) into stg.
    ulonglong2* st2 = (ulonglong2*)stg;
#pragma unroll
    for (int u = 0; u < 4; u++) {
        int r = (qp + 2 * u) * 16 + j;
#pragma unroll
        for (int e = 0; e < 4; e++) {
            int c4 = (eh << 2) + e;
            ulonglong2 v; v.x = acc[u][2*e]; v.y = acc[u][2*e+1];
            st2[r * 16 + (c4 ^ (r & 15))] = v;
        }
    }
    __syncthreads();

    // Coalesced flush: out[b,k,n,:] = x[b,k,n,:] + pos_enc.
    const ulonglong2* xg = (const ulonglong2*)x;
    ulonglong2*       og = (ulonglong2*)out;
#pragma unroll
    for (int i = 0; i < 16; i++) {
        int f    = tid + 128 * i;
        int c4   = f & 15;
        int row  = f >> 4;
        int kk   = kh * 8 + (row >> 4);
        int jj   = row & 15;
        ulonglong2 pv = st2[row * 16 + (c4 ^ (row & 15))];
        size_t gi = ((((size_t)b * KNN + kk) * NPTS) + nt * 16 + jj) * 16 + c4;
        ulonglong2 xv = xg[gi];
        ulonglong2 r;
        asm("add.rn.f32x2 %0, %1, %2;" : "=l"(r.x) : "l"(pv.x), "l"(xv.x));
        asm("add.rn.f32x2 %0, %1, %2;" : "=l"(r.y) : "l"(pv.y), "l"(xv.y));
        og[gi] = r;
    }
}

extern "C" void kernel_launch(void* const* d_in, const int* in_sizes, int n_in,
                              void* d_out, int out_size) {
    const float* xyz = (const float*)d_in[0];
    const float* x   = (const float*)d_in[1];
    const float* W1  = (const float*)d_in[2];
    const float* b1  = (const float*)d_in[3];
    const float* W2  = (const float*)d_in[4];
    const float* b2  = (const float*)d_in[5];
    float* out = (float*)d_out;

    cudaFuncSetAttribute(knn_query, cudaFuncAttributeMaxDynamicSharedMemorySize,
                         QK_SMEM);
    cudaFuncSetAttribute(mlp_kernel, cudaFuncAttributeMaxDynamicSharedMemorySize,
                         MLP_SMEM_FLOATS * (int)sizeof(float));

    grid_build<<<BDIM, 512>>>(xyz);
    knn_query<<<BDIM * (NPTS / QPB), P1T, QK_SMEM>>>();
    mlp_kernel<<<BDIM * 256 * 2, 128, MLP_SMEM_FLOATS * sizeof(float)>>>(
        xyz, x, W1, b1, W2, b2, out);
}

// round 16
// speedup vs baseline: 2.6039x; 1.0313x over previous
#include <cuda_runtime.h>

#define BDIM 8
#define NPTS 4096
#define DDIM 64
#define KNN 16
#define GDIM 8
#define CELLS 512                        // 8x8x8, z-major rows of 64
#define QPB 32                           // queries per block
#define STRIPS 4
#define P1T (QPB * STRIPS)               // 128 threads
#define TILE 512
#define SLICE (TILE / STRIPS)            // 128
#define DEPTH 16
#define GRP 8

typedef unsigned long long ull;

#define INF_KEY ((((ull)0x7F800000u) << 32) | 0xFFFFFFFFull)

__device__ int    g_knn[BDIM * NPTS * KNN];
__device__ float4 g_pts[BDIM * NPTS];          // cell-sorted (x,y,z,|p|^2)
__device__ int    g_oid[BDIM * NPTS];          // original index per sorted slot
__device__ int    g_cs[BDIM * (CELLS + 1)];    // cell start offsets

// key = (float_bits(d) << 32) | original_idx. d >= 0 -> unsigned compare ==
// exact lexicographic (d, idx) == jnp stable argsort; total order => scan
// order irrelevant.
__device__ __forceinline__ ull packK(float d, int m) {
    return ((ull)(unsigned)__float_as_uint(d) << 32) | (unsigned)m;
}

__device__ __forceinline__ void insertK(ull (&key)[KNN], ull ck) {
#pragma unroll
    for (int j = 0; j < KNN; j++) {
        bool lt = ck < key[j];
        ull o = key[j];
        key[j] = lt ? ck : o;
        ck     = lt ? o  : ck;
    }
}

__device__ __forceinline__ float pdist(float4 q, float4 c) {
    float t = q.x * c.x;
    t = fmaf(q.y, c.y, t);
    t = fmaf(q.z, c.z, t);
    return fmaf(-2.0f, t, q.w + c.w);   // identical fp order to passing rounds
}

// ---------------- Phase 0: grid build (R13 geometry: 8 z-slabs) -------------
extern "C" __global__ void __launch_bounds__(512)
grid_build(const float* __restrict__ xyz)
{
    __shared__ int cnt[CELLS];
    __shared__ int cstart[CELLS + 1];
    __shared__ int ofs[CELLS];
    int b = blockIdx.x;
    int tid = threadIdx.x;
    const float* xb = xyz + (size_t)b * NPTS * 3;

    cnt[tid] = 0;
    __syncthreads();

    float px[8], py[8], pz[8]; int cell[8];
#pragma unroll
    for (int u = 0; u < 8; u++) {
        int n = tid + 512 * u;
        float x = xb[3*n], y = xb[3*n+1], z = xb[3*n+2];
        px[u] = x; py[u] = y; pz[u] = z;
        int cx = min(GDIM - 1, (int)(x * 8.0f));
        int cy = min(GDIM - 1, (int)(y * 8.0f));
        int cz = min(GDIM - 1, (int)(z * 8.0f));
        cell[u] = cx + 8 * cy + 64 * cz;        // z-major: slabs contiguous
        atomicAdd(&cnt[cell[u]], 1);
    }
    __syncthreads();

    for (int off = 1; off < CELLS; off <<= 1) {
        int v = (tid >= off) ? cnt[tid - off] : 0;
        __syncthreads();
        cnt[tid] += v;
        __syncthreads();
    }
    if (tid == 0) cstart[0] = 0;
    cstart[tid + 1] = cnt[tid];
    __syncthreads();
    ofs[tid] = cstart[tid];
    g_cs[b * (CELLS + 1) + tid] = cstart[tid];
    if (tid == 511) g_cs[b * (CELLS + 1) + 512] = cstart[512];
    __syncthreads();

#pragma unroll
    for (int u = 0; u < 8; u++) {
        int slot = atomicAdd(&ofs[cell[u]], 1);
        float s = px[u] * px[u];
        s = fmaf(py[u], py[u], s);
        s = fmaf(pz[u], pz[u], s);           // same chain as query side
        g_pts[(size_t)b * NPTS + slot] = make_float4(px[u], py[u], pz[u], s);
        g_oid[(size_t)b * NPTS + slot] = tid + 512 * u;
    }
}

// ---------------- Phase 1: slab top-16 + warp-collective far-tile skip ------
// Sorted slots have non-decreasing slab index, so a staged tile's z-range is
// [slab(first)/8, (slab(last)+1)/8]. If dz_bound^2 > thr + 1e-5 for ALL 32
// lanes (pdist expansion error < 1e-6), no candidate can pass d <= thr ->
// skipping the tile keeps the accepted set bit-identical. Warp-collective
// vote keeps in-loop full-mask syncs safe.
#define QK_SMEM (TILE*16 + TILE*4 + DEPTH*P1T*8)   // 8K + 2K + 16K = 26K

extern "C" __global__ void __launch_bounds__(P1T)
knn_query()
{
    extern __shared__ char smem_raw[];
    float4* cand = (float4*)smem_raw;                        // [TILE]
    int*    soid = (int*)(smem_raw + TILE * 16);             // [TILE]
    ull*    buf  = (ull*)(smem_raw + TILE * 16 + TILE * 4);  // [DEPTH][P1T]

    int blkq = blockIdx.x & 127;
    int b    = blockIdx.x >> 7;
    int tid  = threadIdx.x;
    int lq   = tid & (QPB - 1);
    int s    = tid >> 5;                 // strip 0..3 (warp-uniform)

    const int* cs = g_cs + b * (CELLS + 1);
    size_t pb = (size_t)b * NPTS;

    int qslot = blkq * QPB + lq;
    float4 q = g_pts[pb + qslot];
    int oid  = g_oid[pb + qslot];

    // Block z-range (each warp holds all 32 queries -> identical reduction).
    int slab = min(7, (int)(q.z * 8.0f));
    int zmn = slab, zmx = slab;
#pragma unroll
    for (int o = 16; o > 0; o >>= 1) {
        int a1 = __shfl_xor_sync(0xffffffffu, zmn, o);
        int a2 = __shfl_xor_sync(0xffffffffu, zmx, o);
        zmn = min(zmn, a1); zmx = max(zmx, a2);
    }
    int z0 = max(0, zmn - 2), z1 = min(7, zmx + 2);
    int lo = cs[64 * z0], hi = cs[64 * z1 + 64];   // contiguous slab range
    int C  = hi - lo;
    int ntiles = (C + TILE - 1) >> 9;
    int tqm = (blkq * QPB + 16 - lo) >> 9;          // tile holding the queries
    tqm = min(max(tqm, 0), ntiles - 1);

    ull key[KNN];
#pragma unroll
    for (int j = 0; j < KNN; j++) key[j] = INF_KEY;

    unsigned bufA = (unsigned)__cvta_generic_to_shared(buf) + tid * 8u;
    int cnt = 0;
    float thr = 3.0e38f;
    int up = tqm + 1, dn = tqm - 1;

#pragma unroll 1
    for (int j = 0; j < ntiles; j++) {
        int t;                            // center-out tile order
        if (j == 0) t = tqm;
        else if (up < ntiles && ((j & 1) == 1 || dn < 0)) t = up++;
        else t = dn--;

        __syncthreads();                  // previous tile fully consumed
#pragma unroll
        for (int r = 0; r < TILE / P1T; r++) {     // trivial coalesced copy
            int i = r * P1T + tid;
            int e = t * TILE + i;
            if (e < C) {
                cand[i] = g_pts[pb + lo + e];
                soid[i] = g_oid[pb + lo + e];
            } else {
                cand[i] = make_float4(0.0f, 0.0f, 0.0f, 3.0e38f);
                soid[i] = 0x7fffffff;
            }
        }
        __syncthreads();

        // Tile z-bounds (slab-quantized; slab index non-decreasing in slots).
        int lastR = min(TILE - 1, C - 1 - t * TILE);
        float zminT = (float)min(7, (int)(cand[0].z * 8.0f)) * 0.125f;
        float zmaxT = (float)(min(7, (int)(cand[lastR].z * 8.0f)) + 1) * 0.125f;
        float dzb = fmaxf(fmaxf(zminT - q.z, q.z - zmaxT), 0.0f);
        unsigned far = (dzb * dzb > thr + 1.0e-5f);
        bool skipW = (j > 0) && __all_sync(0xffffffffu, far);
        if (skipW) continue;              // bit-identical accepted set

        int c0 = s * SLICE;
        int start = 0;
        if (j == 0) {                     // seed: 16 convergent inserts
#pragma unroll 1
            for (int i = c0; i < c0 + KNN; i++)
                insertK(key, packK(pdist(q, cand[i]), soid[i]));
            start = KNN;
            thr = __uint_as_float((unsigned)(key[KNN - 1] >> 32));
        }

#pragma unroll 1
        for (int i0 = c0 + start; i0 < c0 + SLICE; i0 += GRP) {
            if (__any_sync(0xffffffffu, cnt > DEPTH - GRP)) {   // drain
                asm volatile("" ::: "memory");
                int cm = cnt;
#pragma unroll
                for (int o = 16; o > 0; o >>= 1) {
                    int t2 = __shfl_xor_sync(0xffffffffu, cm, o);
                    cm = cm > t2 ? cm : t2;
                }
#pragma unroll 2
                for (int jj = 0; jj < cm; jj++) {
                    ull ck = (jj < cnt) ? buf[jj * P1T + tid] : INF_KEY;
                    insertK(key, ck);
                }
                cnt = 0;
                thr = __uint_as_float((unsigned)(key[KNN - 1] >> 32));
            }

            float dv[GRP]; int iv[GRP];
#pragma unroll
            for (int u = 0; u < GRP; u++) {      // 8 independent chains
                dv[u] = pdist(q, cand[i0 + u]);
                iv[u] = soid[i0 + u];
            }
            unsigned h[GRP];
#pragma unroll
            for (int u = 0; u < GRP; u++) h[u] = (dv[u] <= thr);

            unsigned o1 = h[0];
            unsigned s01 = h[0]+h[1], s23 = h[2]+h[3], s45 = h[4]+h[5];
            unsigned o2 = s01, o3 = s01 + h[2], o4 = s01 + s23;
            unsigned o5 = o4 + h[4], o6 = o4 + s45, o7 = o6 + h[6];
            unsigned tot = o7 + h[7];
            unsigned off[GRP] = {0, o1, o2, o3, o4, o5, o6, o7};

#pragma unroll
            for (int u = 0; u < GRP; u++) {      // predicated STS, no clobber
                unsigned ad = bufA + ((unsigned)(cnt + off[u]) << 10); // *P1T*8
                asm volatile(
                    "{\n\t.reg .pred p;\n\t"
                    "setp.ne.u32 p, %0, 0;\n\t"
                    "@p st.shared.v2.u32 [%1], {%2, %3};\n\t}"
                    :: "r"(h[u]), "r"(ad),
                       "r"((unsigned)iv[u]), "r"(__float_as_uint(dv[u])));
            }
            cnt += tot;
        }
    }

    // Final drain.
    asm volatile("" ::: "memory");
    {
        int cm = cnt;
#pragma unroll
        for (int o = 16; o > 0; o >>= 1) {
            int t2 = __shfl_xor_sync(0xffffffffu, cm, o);
            cm = cm > t2 ? cm : t2;
        }
#pragma unroll 2
        for (int jj = 0; jj < cm; jj++) {
            ull ck = (jj < cnt) ? buf[jj * P1T + tid] : INF_KEY;
            insertK(key, ck);
        }
    }

    // Tree strip-merge: s1->s0 || s3->s2, then s2->s0 (exact set merge).
    ull* pairs = buf;
    __syncthreads();
    if (s & 1) {
#pragma unroll
        for (int jj = 0; jj < KNN; jj++)
            pairs[((s >> 1) * QPB + lq) * KNN + jj] = key[jj];
    }
    __syncthreads();
    if (!(s & 1)) {
#pragma unroll
        for (int jj = 0; jj < KNN; jj++)
            insertK(key, pairs[((s >> 1) * QPB + lq) * KNN + jj]);
    }
    __syncthreads();
    if (s == 2) {
#pragma unroll
        for (int jj = 0; jj < KNN; jj++)
            pairs[(2 * QPB + lq) * KNN + jj] = key[jj];
    }
    __syncthreads();

    if (s == 0) {
#pragma unroll
        for (int jj = 0; jj < KNN; jj++)
            insertK(key, pairs[(2 * QPB + lq) * KNN + jj]);

        // Guard: all points outside the z-region are farther than g.
        float d16 = __uint_as_float((unsigned)(key[KNN - 1] >> 32));
        float g = 1.0e30f;
        if (z0 > 0) g = fminf(g, q.z - (float)z0 * 0.125f);
        if (z1 < 7) g = fminf(g, (float)(z1 + 1) * 0.125f - q.z);
        g -= 1.0e-3f;
        if (!(d16 <= g * g)) {           // exact fallback (~never at 0.25 margin)
#pragma unroll
            for (int jj = 0; jj < KNN; jj++) key[jj] = INF_KEY;
#pragma unroll 1
            for (int m = 0; m < NPTS; m++) {
                ull ck = packK(pdist(q, g_pts[pb + m]), g_oid[pb + m]);
                if (ck < key[KNN - 1]) insertK(key, ck);
            }
        }

        int4* kp = (int4*)(g_knn + (pb + oid) * KNN);
        kp[0] = make_int4((int)(unsigned)key[0],  (int)(unsigned)key[1],
                          (int)(unsigned)key[2],  (int)(unsigned)key[3]);
        kp[1] = make_int4((int)(unsigned)key[4],  (int)(unsigned)key[5],
                          (int)(unsigned)key[6],  (int)(unsigned)key[7]);
        kp[2] = make_int4((int)(unsigned)key[8],  (int)(unsigned)key[9],
                          (int)(unsigned)key[10], (int)(unsigned)key[11]);
        kp[3] = make_int4((int)(unsigned)key[12], (int)(unsigned)key[13],
                          (int)(unsigned)key[14], (int)(unsigned)key[15]);
    }
}

// ---------------- Phase 2: MLP + staged transpose-add epilogue --------------
// BYTE-IDENTICAL to R11/R13 (measured 104.5 us, regs=128, 4 blocks/SM).
#define MLP_SMEM_FLOATS (DDIM*DDIM + 4*DDIM + DDIM + 128*DDIM)

extern "C" __global__ void __launch_bounds__(128, 4)
mlp_kernel(const float* __restrict__ xyz, const float* __restrict__ x,
           const float* __restrict__ W1, const float* __restrict__ b1,
           const float* __restrict__ W2, const float* __restrict__ b2,
           float* __restrict__ out)
{
    extern __shared__ float sm[];
    float*  W2s = sm;
    float4* W1p = (float4*)(sm + DDIM*DDIM);
    float*  b2s = sm + DDIM*DDIM + 4*DDIM;
    float*  stg = sm + DDIM*DDIM + 4*DDIM + DDIM;

    int tid = threadIdx.x;
    for (int i = tid; i < DDIM*DDIM; i += 128) W2s[i] = W2[i];
    if (tid < DDIM) {
        W1p[tid] = make_float4(W1[tid], W1[DDIM + tid], W1[2*DDIM + tid], b1[tid]);
        b2s[tid] = b2[tid];
    }
    __syncthreads();

    int kh = blockIdx.x & 1;
    int nt = (blockIdx.x >> 1) & 255;
    int b  = blockIdx.x >> 9;
    int j  = tid & 15;
    int qp = (tid >> 4) & 1;
    int eh = tid >> 5;
    int n  = nt * 16 + j;

    const int* kr = g_knn + (((size_t)b * NPTS + n) << 4) + kh * 8 + qp;
    const float* xb = xyz + (size_t)b * NPTS * 3;
    float px = xb[3*n], py = xb[3*n+1], pz = xb[3*n+2];

    float dx[4], dy[4], dz[4];
#pragma unroll
    for (int u = 0; u < 4; u++) {
        int m = kr[2 * u];
        dx[u] = px - xb[3*m];
        dy[u] = py - xb[3*m+1];
        dz[u] = pz - xb[3*m+2];
    }

    ull acc[4][8];
    const ull* b2p = (const ull*)(b2s + (eh << 4));
#pragma unroll
    for (int u = 0; u < 4; u++)
#pragma unroll
        for (int e = 0; e < 8; e++) acc[u][e] = b2p[e];

#pragma unroll 4
    for (int d = 0; d < DDIM; d++) {
        float4 w1 = W1p[d];
        float h[4];
        unsigned z = 1;
#pragma unroll
        for (int u = 0; u < 4; u++) {
            h[u] = fmaf(dz[u], w1.z, fmaf(dy[u], w1.y, fmaf(dx[u], w1.x, w1.w)));
            h[u] = fmaxf(h[u], 0.0f);
            z &= (h[u] == 0.0f);
        }
        if (__all_sync(0xffffffffu, z)) continue;
        ull h2[4];
#pragma unroll
        for (int u = 0; u < 4; u++)
            asm("mov.b64 %0, {%1, %1};" : "=l"(h2[u]) : "r"(__float_as_int(h[u])));
        const ulonglong2* w = (const ulonglong2*)(W2s + (d << 6) + (eh << 4));
#pragma unroll
        for (int e = 0; e < 4; e++) {
            ulonglong2 wv = w[e];
#pragma unroll
            for (int u = 0; u < 4; u++) {
                asm("fma.rn.f32x2 %0, %1, %2, %0;" : "+l"(acc[u][2*e])   : "l"(h2[u]), "l"(wv.x));
                asm("fma.rn.f32x2 %0, %1, %2, %0;" : "+l"(acc[u][2*e+1]) : "l"(h2[u]), "l"(wv.y));
            }
        }
    }

    ulonglong2* st2 = (ulonglong2*)stg;
#pragma unroll
    for (int u = 0; u < 4; u++) {
        int r = (qp + 2 * u) * 16 + j;
#pragma unroll
        for (int e = 0; e < 4; e++) {
            int c4 = (eh << 2) + e;
            ulonglong2 v; v.x = acc[u][2*e]; v.y = acc[u][2*e+1];
            st2[r * 16 + (c4 ^ (r & 15))] = v;
        }
    }
    __syncthreads();

    const ulonglong2* xg = (const ulonglong2*)x;
    ulonglong2*       og = (ulonglong2*)out;
#pragma unroll
    for (int i = 0; i < 16; i++) {
        int f    = tid + 128 * i;
        int c4   = f & 15;
        int row  = f >> 4;
        int kk   = kh * 8 + (row >> 4);
        int jj   = row & 15;
        ulonglong2 pv = st2[row * 16 + (c4 ^ (row & 15))];
        size_t gi = ((((size_t)b * KNN + kk) * NPTS) + nt * 16 + jj) * 16 + c4;
        ulonglong2 xv = xg[gi];
        ulonglong2 r;
        asm("add.rn.f32x2 %0, %1, %2;" : "=l"(r.x) : "l"(pv.x), "l"(xv.x));
        asm("add.rn.f32x2 %0, %1, %2;" : "=l"(r.y) : "l"(pv.y), "l"(xv.y));
        og[gi] = r;
    }
}

extern "C" void kernel_launch(void* const* d_in, const int* in_sizes, int n_in,
                              void* d_out, int out_size) {
    const float* xyz = (const float*)d_in[0];
    const float* x   = (const float*)d_in[1];
    const float* W1  = (const float*)d_in[2];
    const float* b1  = (const float*)d_in[3];
    const float* W2  = (const float*)d_in[4];
    const float* b2  = (const float*)d_in[5];
    float* out = (float*)d_out;

    cudaFuncSetAttribute(knn_query, cudaFuncAttributeMaxDynamicSharedMemorySize,
                         QK_SMEM);
    cudaFuncSetAttribute(mlp_kernel, cudaFuncAttributeMaxDynamicSharedMemorySize,
                         MLP_SMEM_FLOATS * (int)sizeof(float));

    grid_build<<<BDIM, 512>>>(xyz);
    knn_query<<<BDIM * (NPTS / QPB), P1T, QK_SMEM>>>();
    mlp_kernel<<<BDIM * 256 * 2, 128, MLP_SMEM_FLOATS * sizeof(float)>>>(
        xyz, x, W1, b1, W2, b2, out);
}